// round 13
// baseline (speedup 1.0000x reference)
#include <cuda_runtime.h>
#include <cuda_fp16.h>
#include <cstdint>
#include <math.h>

#define N_DIM 1024
#define K_DIM 1024
#define NELEM 33554432  // 4*8192*1024

#define MT 128
#define NT 128
#define KT 64
#define KITERS 16
#define STAGES 3
#define STAGE_BYTES 32768                 // A 16KB + B 16KB (fp16)
#define SMEM_TOTAL (STAGES * STAGE_BYTES) // 96KB

// Scratch (device globals; zero-initialized)
__device__ __half    g_WkR[1048576];
__device__ __half    g_WqR[1048576];
__device__ __half    g_Vh[NELEM];
__device__ uint32_t  g_KS[NELEM];        // (cos,sin) of key phase, fp16x2
__device__ uint32_t  g_QS[NELEM];        // (cos,sin) of query phase, fp16x2
__device__ __half    g_R [NELEM];
__device__ __half    g_X [NELEM];
__device__ __half    g_WT[6 * 1024 * 1024];
__device__ float2    g_stats[32768];
__device__ float     g_gWo[1024];
__device__ float     g_bWoBo[1024];
__device__ float     g_bck[1024];
__device__ float     g_bcq[1024];
__device__ float     g_zero[1024];

// ---------------- helpers ----------------
__device__ __forceinline__ uint32_t smem_u32(const void* p) {
    uint32_t a;
    asm("{ .reg .u64 t; cvta.to.shared.u64 t, %1; cvt.u32.u64 %0, t; }" : "=r"(a) : "l"(p));
    return a;
}
__device__ __forceinline__ void cp16(uint32_t dst, const void* src) {
    asm volatile("cp.async.cg.shared.global [%0], [%1], 16;\n" :: "r"(dst), "l"(src) : "memory");
}
__device__ __forceinline__ void cp_commit() {
    asm volatile("cp.async.commit_group;\n" ::: "memory");
}
template <int N> __device__ __forceinline__ void cp_wait() {
    asm volatile("cp.async.wait_group %0;\n" :: "n"(N) : "memory");
}
__device__ __forceinline__ void ldmx4(uint32_t& r0, uint32_t& r1, uint32_t& r2, uint32_t& r3,
                                      uint32_t addr) {
    asm volatile("ldmatrix.sync.aligned.m8n8.x4.shared.b16 {%0,%1,%2,%3}, [%4];"
                 : "=r"(r0), "=r"(r1), "=r"(r2), "=r"(r3) : "r"(addr));
}
// fp16 MMA, f32 accumulate
__device__ __forceinline__ void mma_f16(float c[4],
    uint32_t a0, uint32_t a1, uint32_t a2, uint32_t a3, uint32_t b0, uint32_t b1)
{
    asm volatile(
        "mma.sync.aligned.m16n8k16.row.col.f32.f16.f16.f32 "
        "{%0,%1,%2,%3}, {%4,%5,%6,%7}, {%8,%9}, {%0,%1,%2,%3};\n"
        : "+f"(c[0]), "+f"(c[1]), "+f"(c[2]), "+f"(c[3])
        : "r"(a0), "r"(a1), "r"(a2), "r"(a3), "r"(b0), "r"(b1));
}

struct GArgs {
    const __half* A[3];
    const __half* W[3];
    const float*  b[3];
    void*         C[3];
    int epi[3];               // 0: +bias  1: tanh->sincos fp16x2  3: LN-affine+residual
    int oh[3];                // epi0: 1 = store fp16
    const float* ps;          // epi1
    const float* resid;       // epi3: x
    const float2* stats;      // epi3: (rstd, mu*rstd)
    const float* gWo;         // epi3
};

// ---------------- GEMM (fp16 in, f32 acc, z-batched, runtime epilogue) ----------------
// 128 threads (4 warps), warp tile 64x64: LDSM amplification A x2, B x2
// (64KB reads/kt vs 96KB with 8x 32x64 warps) -> shared port no longer binds.
__global__ void __launch_bounds__(128, 2)
gemm_rt(const GArgs args)
{
    extern __shared__ char smem[];
    const uint32_t tileBase = smem_u32(smem);

    const int z = blockIdx.z;
    const __half* A    = args.A[z];
    const __half* WT   = args.W[z];
    const float*  bias = args.b[z];
    void*         C    = args.C[z];
    const int     epi  = args.epi[z];
    const int     oh   = args.oh[z];

    const int tid  = threadIdx.x;
    const int wid  = tid >> 5;
    const int lane = tid & 31;
    const int wm   = wid >> 1;        // 0..1 : 64-row strip
    const int wn   = wid & 1;         // 0..1 : 64-col strip
    const int g    = lane >> 2;
    const int tg   = lane & 3;

    const long bm0 = (long)blockIdx.y * MT;
    const int  bn0 = blockIdx.x * NT;

    const __half* Abase = A  + bm0 * K_DIM;
    const __half* Bbase = WT + (long)bn0 * K_DIM;

    // rows 128B apart (64 fp16), 8 chunks of 16B, XOR-swizzled by row&7
    const uint32_t rsw   = lane & 7;
    const uint32_t aoff0 = (uint32_t)((wm * 64 + ((lane >> 3) & 1) * 8 + (lane & 7)) * 128);
    const uint32_t hbitA = (lane >> 4) & 1;
    const uint32_t boff0 = (uint32_t)((wn * 64 + ((lane >> 4) & 1) * 8 + (lane & 7)) * 128) + 16384u;
    const uint32_t hbitB = (lane >> 3) & 1;

    auto fill = [&](int s) {
        const uint32_t buf = tileBase + (uint32_t)(s % STAGES) * STAGE_BYTES;
        const int k0 = s * KT;
        #pragma unroll
        for (int i = 0; i < 8; i++) {          // A: 128 rows x 8 chunks = 1024 cp16
            int o = tid + 128 * i;
            int row = o >> 3, c = o & 7;
            cp16(buf + (uint32_t)(row * 128 + ((c ^ (row & 7)) << 4)),
                 Abase + (long)row * K_DIM + k0 + c * 8);
        }
        #pragma unroll
        for (int i = 0; i < 8; i++) {          // B
            int o = tid + 128 * i;
            int row = o >> 3, c = o & 7;
            cp16(buf + 16384u + (uint32_t)(row * 128 + ((c ^ (row & 7)) << 4)),
                 Bbase + (long)row * K_DIM + k0 + c * 8);
        }
        cp_commit();
    };

    float acc[4][8][4];
    #pragma unroll
    for (int i = 0; i < 4; i++)
        #pragma unroll
        for (int j = 0; j < 8; j++)
            #pragma unroll
            for (int k = 0; k < 4; k++)
                acc[i][j][k] = 0.f;

    fill(0);
    fill(1);

    #pragma unroll 1
    for (int kt = 0; kt < KITERS; kt++) {
        if (kt < KITERS - 1) cp_wait<1>(); else cp_wait<0>();
        __syncthreads();
        if (kt < KITERS - 2) fill(kt + 2);

        const uint32_t sbase = tileBase + (uint32_t)(kt % STAGES) * STAGE_BYTES;
        #pragma unroll
        for (int kk = 0; kk < 4; kk++) {       // K=16 per kk
            uint32_t af[4][4], bf[8][2];
            const uint32_t cA = ((uint32_t)(kk * 2) + hbitA) ^ rsw;
            const uint32_t cB = ((uint32_t)(kk * 2) + hbitB) ^ rsw;
            #pragma unroll
            for (int im = 0; im < 4; im++)
                ldmx4(af[im][0], af[im][1], af[im][2], af[im][3],
                      sbase + aoff0 + (uint32_t)(im * 2048) + (cA << 4));
            #pragma unroll
            for (int q = 0; q < 4; q++)
                ldmx4(bf[2 * q][0], bf[2 * q][1], bf[2 * q + 1][0], bf[2 * q + 1][1],
                      sbase + boff0 + (uint32_t)(q * 2048) + (cB << 4));
            #pragma unroll
            for (int im = 0; im < 4; im++)
                #pragma unroll
                for (int in = 0; in < 8; in++)
                    mma_f16(acc[im][in],
                            af[im][0], af[im][1], af[im][2], af[im][3],
                            bf[in][0], bf[in][1]);
        }
    }

    // Epilogue
    #pragma unroll
    for (int im = 0; im < 4; im++) {
        #pragma unroll
        for (int in = 0; in < 8; in++) {
            const int col = bn0 + wn * 64 + in * 8 + 2 * tg;
            const float b0 = __ldg(bias + col);
            const float b1 = __ldg(bias + col + 1);
            #pragma unroll
            for (int h = 0; h < 2; h++) {
                const long row = bm0 + wm * 64 + im * 16 + g + h * 8;
                float v0 = acc[im][in][2 * h + 0] + b0;
                float v1 = acc[im][in][2 * h + 1] + b1;
                if (epi == 3) {
                    const float2 st = __ldg(args.stats + row);
                    v0 = st.x * acc[im][in][2 * h + 0] - st.y * __ldg(args.gWo + col) + b0
                         + args.resid[row * N_DIM + col];
                    v1 = st.x * acc[im][in][2 * h + 1] - st.y * __ldg(args.gWo + col + 1) + b1
                         + args.resid[row * N_DIM + col + 1];
                    *(float2*)((float*)C + row * N_DIM + col) = make_float2(v0, v1);
                } else if (epi == 1) {
                    float p0 = tanhf(v0) * __ldg(args.ps + col);
                    float p1 = tanhf(v1) * __ldg(args.ps + col + 1);
                    float s0, c0, s1, c1;
                    __sincosf(p0, &s0, &c0);
                    __sincosf(p1, &s1, &c1);
                    __half2 h0 = __floats2half2_rn(c0, s0);
                    __half2 h1 = __floats2half2_rn(c1, s1);
                    uint2 pk = make_uint2(*(uint32_t*)&h0, *(uint32_t*)&h1);
                    *(uint2*)((uint32_t*)C + row * N_DIM + col) = pk;
                } else {
                    if (oh) {
                        *(__half2*)((__half*)C + row * N_DIM + col) = __floats2half2_rn(v0, v1);
                    } else {
                        *(float2*)((float*)C + row * N_DIM + col) = make_float2(v0, v1);
                    }
                }
            }
        }
    }
}

// ---------------- prep kernels ----------------
struct W4 { const float* w[4]; };

__global__ void __launch_bounds__(256)
wtrans_all_k(const W4 ws, __half* __restrict__ WT)
{
    __shared__ float t[32][33];
    static const int slot[4] = {0, 1, 2, 5};
    const float* W = ws.w[blockIdx.z];
    __half* D = WT + (long)slot[blockIdx.z] * 1048576;
    int bx = blockIdx.x * 32, by = blockIdx.y * 32;
    #pragma unroll
    for (int i = threadIdx.y; i < 32; i += 8)
        t[i][threadIdx.x] = W[(by + i) * 1024 + bx + threadIdx.x];
    __syncthreads();
    #pragma unroll
    for (int i = threadIdx.y; i < 32; i += 8)
        D[(bx + i) * 1024 + by + threadIdx.x] = __float2half_rn(t[threadIdx.x][i]);
}

__global__ void __launch_bounds__(256)
cvt2_h_k(const float* __restrict__ s0, __half* __restrict__ d0,
         const float* __restrict__ s1, __half* __restrict__ d1)
{
    const float* s = blockIdx.y ? s1 : s0;
    __half* d = blockIdx.y ? d1 : d0;
    long i = ((long)blockIdx.x * 256 + threadIdx.x) * 8;
    float4 v0 = *(const float4*)(s + i);
    float4 v1 = *(const float4*)(s + i + 4);
    __half2 h[4];
    h[0] = __floats2half2_rn(v0.x, v0.y);
    h[1] = __floats2half2_rn(v0.z, v0.w);
    h[2] = __floats2half2_rn(v1.x, v1.y);
    h[3] = __floats2half2_rn(v1.z, v1.w);
    *(uint4*)(d + i) = *(uint4*)h;
}

__global__ void __launch_bounds__(256)
cvt_h_k(const float* __restrict__ s, __half* __restrict__ d)
{
    long i = ((long)blockIdx.x * 256 + threadIdx.x) * 8;
    float4 v0 = *(const float4*)(s + i);
    float4 v1 = *(const float4*)(s + i + 4);
    __half2 h[4];
    h[0] = __floats2half2_rn(v0.x, v0.y);
    h[1] = __floats2half2_rn(v0.z, v0.w);
    h[2] = __floats2half2_rn(v1.x, v1.y);
    h[3] = __floats2half2_rn(v1.z, v1.w);
    *(uint4*)(d + i) = *(uint4*)h;
}

// GEMVs from fp16 transposed weights: one warp per column, half2 loads.
__global__ void __launch_bounds__(128)
gemv_prep_k(const __half* __restrict__ WoT, const __half* __restrict__ WkpT,
            const __half* __restrict__ WqpT,
            const float* __restrict__ g, const float* __restrict__ b,
            const float* __restrict__ bo,
            const float* __restrict__ bk, const float* __restrict__ bkp,
            const float* __restrict__ bq, const float* __restrict__ bqp,
            float* __restrict__ gWo, float* __restrict__ bWoBo,
            float* __restrict__ bck, float* __restrict__ bcq)
{
    const int lane = threadIdx.x & 31;
    const int col  = blockIdx.x * 4 + (threadIdx.x >> 5);
    const __half* wo  = WoT  + (long)col * 1024;
    const __half* wkp = WkpT + (long)col * 1024;
    const __half* wqp = WqpT + (long)col * 1024;
    float a1 = 0.f, a2 = 0.f, a3 = 0.f, a4 = 0.f;
    #pragma unroll 8
    for (int d = lane * 2; d < 1024; d += 64) {
        float2 w  = __half22float2(*(const __half2*)(wo + d));
        float2 wk = __half22float2(*(const __half2*)(wkp + d));
        float2 wq = __half22float2(*(const __half2*)(wqp + d));
        float2 gg = *(const float2*)(g + d);
        float2 bb = *(const float2*)(b + d);
        float2 kk = *(const float2*)(bk + d);
        float2 qq = *(const float2*)(bq + d);
        a1 = fmaf(gg.x, w.x, fmaf(gg.y, w.y, a1));
        a2 = fmaf(bb.x, w.x, fmaf(bb.y, w.y, a2));
        a3 = fmaf(kk.x, wk.x, fmaf(kk.y, wk.y, a3));
        a4 = fmaf(qq.x, wq.x, fmaf(qq.y, wq.y, a4));
    }
    #pragma unroll
    for (int o = 16; o; o >>= 1) {
        a1 += __shfl_xor_sync(0xffffffffu, a1, o);
        a2 += __shfl_xor_sync(0xffffffffu, a2, o);
        a3 += __shfl_xor_sync(0xffffffffu, a3, o);
        a4 += __shfl_xor_sync(0xffffffffu, a4, o);
    }
    if (lane == 0) {
        gWo[col]   = a1;
        bWoBo[col] = a2 + bo[col];
        bck[col]   = a3 + bkp[col];
        bcq[col]   = a4 + bqp[col];
    }
}

// ---------------- bind + chunk scan (pure FMA; cos/sin precomputed fp16x2) ----------------
__global__ void __launch_bounds__(256)
bind_scan_k(const __half* __restrict__ V, const uint32_t* __restrict__ KS,
            const uint32_t* __restrict__ QS, const float* __restrict__ lng,
            __half* __restrict__ R, float2* __restrict__ stats)
{
    __shared__ float2 part[64][8];
    const float inv = 0.03125f;  // 1/sqrt(1024)
    const int tid = threadIdx.x;
    const int lane = tid & 31, w = tid >> 5;
    long idx = (long)blockIdx.x * 64 * 1024 + tid * 4;
    float4 mr = make_float4(0.f, 0.f, 0.f, 0.f);
    float4 mi = make_float4(0.f, 0.f, 0.f, 0.f);
    const float4 gv = *(const float4*)(lng + tid * 4);

    #pragma unroll 4
    for (int s = 0; s < 64; s++, idx += 1024) {
        uint2 vpk = *(const uint2*)(V + idx);
        uint4 ks  = *(const uint4*)(KS + idx);
        uint4 qs  = *(const uint4*)(QS + idx);
        float2 va = __half22float2(*(__half2*)&vpk.x);
        float2 vb = __half22float2(*(__half2*)&vpk.y);
        float2 k0 = __half22float2(*(__half2*)&ks.x);
        float2 k1 = __half22float2(*(__half2*)&ks.y);
        float2 k2 = __half22float2(*(__half2*)&ks.z);
        float2 k3 = __half22float2(*(__half2*)&ks.w);
        float2 q0 = __half22float2(*(__half2*)&qs.x);
        float2 q1 = __half22float2(*(__half2*)&qs.y);
        float2 q2 = __half22float2(*(__half2*)&qs.z);
        float2 q3 = __half22float2(*(__half2*)&qs.w);
        float4 out;

        mr.x = fmaf(va.x, k0.x, mr.x); mi.x = fmaf(va.x, k0.y, mi.x);
        out.x = (mr.x * q0.x + mi.x * q0.y) * inv;
        mr.y = fmaf(va.y, k1.x, mr.y); mi.y = fmaf(va.y, k1.y, mi.y);
        out.y = (mr.y * q1.x + mi.y * q1.y) * inv;
        mr.z = fmaf(vb.x, k2.x, mr.z); mi.z = fmaf(vb.x, k2.y, mi.z);
        out.z = (mr.z * q2.x + mi.z * q2.y) * inv;
        mr.w = fmaf(vb.y, k3.x, mr.w); mi.w = fmaf(vb.y, k3.y, mi.w);
        out.w = (mr.w * q3.x + mi.w * q3.y) * inv;

        float rs = out.x + out.y + out.z + out.w;
        float rq = out.x * out.x + out.y * out.y + out.z * out.z + out.w * out.w;
        #pragma unroll
        for (int o = 16; o; o >>= 1) {
            rs += __shfl_xor_sync(0xffffffffu, rs, o);
            rq += __shfl_xor_sync(0xffffffffu, rq, o);
        }
        if (lane == 0) part[s][w] = make_float2(rs, rq);

        __half2 h0 = __floats2half2_rn(out.x * gv.x, out.y * gv.y);
        __half2 h1 = __floats2half2_rn(out.z * gv.z, out.w * gv.w);
        uint2 pk = make_uint2(*(uint32_t*)&h0, *(uint32_t*)&h1);
        *(uint2*)(R + idx) = pk;
    }
    __syncthreads();
    if (tid < 64) {
        float S = 0.f, Q = 0.f;
        #pragma unroll
        for (int i = 0; i < 8; i++) { S += part[tid][i].x; Q += part[tid][i].y; }
        float mu = S * (1.f / 1024.f);
        float var = Q * (1.f / 1024.f) - mu * mu;
        float rstd = rsqrtf(var + 1e-5f);
        stats[blockIdx.x * 64 + tid] = make_float2(rstd, mu * rstd);
    }
}

extern "C" void kernel_launch(void* const* d_in, const int* in_sizes, int n_in,
                              void* d_out, int out_size)
{
    const float* x   = (const float*)d_in[0];
    const float* Wk  = (const float*)d_in[1];
    const float* bk  = (const float*)d_in[2];
    const float* Wv  = (const float*)d_in[3];
    const float* bv  = (const float*)d_in[4];
    const float* Wq  = (const float*)d_in[5];
    const float* bq  = (const float*)d_in[6];
    const float* Wkp = (const float*)d_in[7];
    const float* bkp = (const float*)d_in[8];
    const float* Wqp = (const float*)d_in[9];
    const float* bqp = (const float*)d_in[10];
    const float* ps  = (const float*)d_in[11];
    const float* lng = (const float*)d_in[12];
    const float* lnb = (const float*)d_in[13];
    const float* Wo  = (const float*)d_in[14];
    const float* bo  = (const float*)d_in[15];
    float* out = (float*)d_out;

    const int M = in_sizes[0] / 1024;  // 32768

    uint32_t *pKS, *pQS;
    __half *pVh, *pR, *pX, *pWT, *pWkR, *pWqR;
    float *pgWo, *pbWoBo, *pbck, *pbcq, *pzero;
    float2* pStats;
    cudaGetSymbolAddress((void**)&pVh,  g_Vh);
    cudaGetSymbolAddress((void**)&pKS,  g_KS);
    cudaGetSymbolAddress((void**)&pQS,  g_QS);
    cudaGetSymbolAddress((void**)&pR,   g_R);
    cudaGetSymbolAddress((void**)&pX,   g_X);
    cudaGetSymbolAddress((void**)&pWT,  g_WT);
    cudaGetSymbolAddress((void**)&pWkR, g_WkR);
    cudaGetSymbolAddress((void**)&pWqR, g_WqR);
    cudaGetSymbolAddress((void**)&pStats, g_stats);
    cudaGetSymbolAddress((void**)&pgWo, g_gWo);
    cudaGetSymbolAddress((void**)&pbWoBo, g_bWoBo);
    cudaGetSymbolAddress((void**)&pbck, g_bck);
    cudaGetSymbolAddress((void**)&pbcq, g_bcq);
    cudaGetSymbolAddress((void**)&pzero, g_zero);

    cudaFuncSetAttribute(gemm_rt, cudaFuncAttributeMaxDynamicSharedMemorySize, SMEM_TOTAL);

    // ---- forked prep: s2 runs cvtX -> gemv while default runs cvt2 -> wtrans -> comp ----
    cudaStream_t s2;
    cudaStreamCreateWithFlags(&s2, cudaStreamNonBlocking);
    cudaEvent_t ev0, evW, evG;
    cudaEventCreateWithFlags(&ev0, cudaEventDisableTiming);
    cudaEventCreateWithFlags(&evW, cudaEventDisableTiming);
    cudaEventCreateWithFlags(&evG, cudaEventDisableTiming);

    cudaEventRecord(ev0, 0);
    cudaStreamWaitEvent(s2, ev0, 0);

    cvt_h_k<<<NELEM / 2048, 256, 0, s2>>>(x, pX);

    W4 ws;
    ws.w[0] = Wv; ws.w[1] = Wkp; ws.w[2] = Wqp; ws.w[3] = Wo;
    cvt2_h_k<<<dim3(512, 2), 256>>>(Wk, pWkR, Wq, pWqR);
    wtrans_all_k<<<dim3(32, 32, 4), dim3(32, 8)>>>(ws, pWT);
    cudaEventRecord(evW, 0);
    cudaStreamWaitEvent(s2, evW, 0);

    gemv_prep_k<<<256, 128, 0, s2>>>(pWT + 5 * 1048576, pWT + 1 * 1048576, pWT + 2 * 1048576,
                                     lng, lnb, bo, bk, bkp, bq, bqp,
                                     pgWo, pbWoBo, pbck, pbcq);
    cudaEventRecord(evG, s2);

    GArgs a{};
    a.ps = ps; a.resid = x; a.stats = pStats; a.gWo = pgWo;

    // Weight composition on default: WckT -> slot3 ; WcqT -> slot4 (fp16 out)
    a.A[0] = pWT + 1 * 1048576; a.A[1] = pWT + 2 * 1048576; a.A[2] = a.A[1];
    a.W[0] = pWkR;              a.W[1] = pWqR;              a.W[2] = a.W[1];
    a.b[0] = pzero; a.b[1] = pzero; a.b[2] = pzero;
    a.C[0] = pWT + 3 * 1048576; a.C[1] = pWT + 4 * 1048576; a.C[2] = a.C[1];
    a.epi[0] = 0; a.epi[1] = 0; a.epi[2] = 0;
    a.oh[0] = 1; a.oh[1] = 1; a.oh[2] = 1;
    gemm_rt<<<dim3(8, 8, 2), 128, SMEM_TOTAL>>>(a);

    cudaStreamWaitEvent(0, evG, 0);

    // Big batch: V(fp16) ; KS = cos/sin(tanh(X@WckT+bck)*ps) ; QS likewise
    a.A[0] = pX; a.A[1] = pX; a.A[2] = pX;
    a.W[0] = pWT + 0 * 1048576; a.W[1] = pWT + 3 * 1048576; a.W[2] = pWT + 4 * 1048576;
    a.b[0] = bv; a.b[1] = pbck; a.b[2] = pbcq;
    a.C[0] = pVh; a.C[1] = pKS; a.C[2] = pQS;
    a.epi[0] = 0; a.epi[1] = 1; a.epi[2] = 1;
    a.oh[0] = 1; a.oh[1] = 0; a.oh[2] = 0;
    gemm_rt<<<dim3(N_DIM / NT, M / MT, 3), 128, SMEM_TOTAL>>>(a);

    bind_scan_k<<<M / 64, 256>>>(pVh, pKS, pQS, lng, pR, pStats);

    // Output GEMM with fused LayerNorm-affine + residual
    a.A[0] = pR; a.A[1] = pR; a.A[2] = pR;
    a.W[0] = pWT + 5 * 1048576; a.W[1] = a.W[0]; a.W[2] = a.W[0];
    a.b[0] = pbWoBo; a.b[1] = pbWoBo; a.b[2] = pbWoBo;
    a.C[0] = out; a.C[1] = out; a.C[2] = out;
    a.epi[0] = 3; a.epi[1] = 3; a.epi[2] = 3;
    a.oh[0] = 0; a.oh[1] = 0; a.oh[2] = 0;
    gemm_rt<<<dim3(N_DIM / NT, M / MT, 1), 128, SMEM_TOTAL>>>(a);
}

// round 15
// speedup vs baseline: 1.1934x; 1.1934x over previous
#include <cuda_runtime.h>
#include <cuda_fp16.h>
#include <cstdint>
#include <math.h>

#define N_DIM 1024
#define K_DIM 1024
#define NELEM 33554432  // 4*8192*1024

#define MT 128
#define NT 128
#define KT 64
#define KITERS 16
#define STAGES 3
#define STAGE_BYTES 32768                 // A 16KB + B 16KB (fp16)
#define SMEM_TOTAL (STAGES * STAGE_BYTES) // 96KB

// Scratch (device globals; zero-initialized)
__device__ __half    g_WkR[1048576];
__device__ __half    g_WqR[1048576];
__device__ __half    g_Vh[NELEM];
__device__ uint32_t  g_KS[NELEM];        // (cos,sin) of key phase, fp16x2
__device__ uint32_t  g_QS[NELEM];        // (cos,sin) of query phase, fp16x2
__device__ __half    g_R [NELEM];
__device__ __half    g_X [NELEM];
__device__ __half    g_WT[6 * 1024 * 1024];
__device__ float2    g_stats[32768];
__device__ float     g_gWo[1024];
__device__ float     g_bWoBo[1024];
__device__ float     g_bck[1024];
__device__ float     g_bcq[1024];
__device__ float     g_zero[1024];

// ---------------- helpers ----------------
__device__ __forceinline__ uint32_t smem_u32(const void* p) {
    uint32_t a;
    asm("{ .reg .u64 t; cvta.to.shared.u64 t, %1; cvt.u32.u64 %0, t; }" : "=r"(a) : "l"(p));
    return a;
}
__device__ __forceinline__ void cp16(uint32_t dst, const void* src) {
    asm volatile("cp.async.cg.shared.global [%0], [%1], 16;\n" :: "r"(dst), "l"(src) : "memory");
}
__device__ __forceinline__ void cp_commit() {
    asm volatile("cp.async.commit_group;\n" ::: "memory");
}
template <int N> __device__ __forceinline__ void cp_wait() {
    asm volatile("cp.async.wait_group %0;\n" :: "n"(N) : "memory");
}
__device__ __forceinline__ void ldmx4(uint32_t& r0, uint32_t& r1, uint32_t& r2, uint32_t& r3,
                                      uint32_t addr) {
    asm volatile("ldmatrix.sync.aligned.m8n8.x4.shared.b16 {%0,%1,%2,%3}, [%4];"
                 : "=r"(r0), "=r"(r1), "=r"(r2), "=r"(r3) : "r"(addr));
}
// fp16 MMA, f32 accumulate
__device__ __forceinline__ void mma_f16(float c[4],
    uint32_t a0, uint32_t a1, uint32_t a2, uint32_t a3, uint32_t b0, uint32_t b1)
{
    asm volatile(
        "mma.sync.aligned.m16n8k16.row.col.f32.f16.f16.f32 "
        "{%0,%1,%2,%3}, {%4,%5,%6,%7}, {%8,%9}, {%0,%1,%2,%3};\n"
        : "+f"(c[0]), "+f"(c[1]), "+f"(c[2]), "+f"(c[3])
        : "r"(a0), "r"(a1), "r"(a2), "r"(a3), "r"(b0), "r"(b1));
}

struct GArgs {
    const __half* A[3];
    const __half* W[3];
    const float*  b[3];
    void*         C[3];
    int epi[3];               // 0: +bias  1: tanh->sincos fp16x2  3: LN-affine+residual
    int oh[3];                // epi0: 1 = store fp16
    const float* ps;          // epi1
    const float* resid;       // epi3: x (pre-offset per M-half)
    const float2* stats;      // epi3: (rstd, mu*rstd) (pre-offset)
    const float* gWo;         // epi3
};

// ---------------- GEMM (fp16 in, f32 acc, z-batched, runtime epilogue) ----------------
// 256 threads (8 warps), warp tile 32x64, 3-stage cp.async (R12-proven core).
__global__ void __launch_bounds__(256, 2)
gemm_rt(const GArgs args)
{
    extern __shared__ char smem[];
    const uint32_t tileBase = smem_u32(smem);

    const int z = blockIdx.z;
    const __half* A    = args.A[z];
    const __half* WT   = args.W[z];
    const float*  bias = args.b[z];
    void*         C    = args.C[z];
    const int     epi  = args.epi[z];
    const int     oh   = args.oh[z];

    const int tid  = threadIdx.x;
    const int wid  = tid >> 5;
    const int lane = tid & 31;
    const int wm   = wid >> 1;
    const int wn   = wid & 1;
    const int g    = lane >> 2;
    const int tg   = lane & 3;

    const long bm0 = (long)blockIdx.y * MT;
    const int  bn0 = blockIdx.x * NT;

    const __half* Abase = A  + bm0 * K_DIM;
    const __half* Bbase = WT + (long)bn0 * K_DIM;

    const uint32_t rsw   = lane & 7;
    const uint32_t aoff0 = (uint32_t)((wm * 32 + ((lane >> 3) & 1) * 8 + (lane & 7)) * 128);
    const uint32_t hbitA = (lane >> 4) & 1;
    const uint32_t boff0 = (uint32_t)((wn * 64 + ((lane >> 4) & 1) * 8 + (lane & 7)) * 128) + 16384u;
    const uint32_t hbitB = (lane >> 3) & 1;

    auto fill = [&](int s) {
        const uint32_t buf = tileBase + (uint32_t)(s % STAGES) * STAGE_BYTES;
        const int k0 = s * KT;
        #pragma unroll
        for (int i = 0; i < 4; i++) {
            int o = tid + 256 * i;
            int row = o >> 3, c = o & 7;
            cp16(buf + (uint32_t)(row * 128 + ((c ^ (row & 7)) << 4)),
                 Abase + (long)row * K_DIM + k0 + c * 8);
        }
        #pragma unroll
        for (int i = 0; i < 4; i++) {
            int o = tid + 256 * i;
            int row = o >> 3, c = o & 7;
            cp16(buf + 16384u + (uint32_t)(row * 128 + ((c ^ (row & 7)) << 4)),
                 Bbase + (long)row * K_DIM + k0 + c * 8);
        }
        cp_commit();
    };

    float acc[2][8][4];
    #pragma unroll
    for (int i = 0; i < 2; i++)
        #pragma unroll
        for (int j = 0; j < 8; j++)
            #pragma unroll
            for (int k = 0; k < 4; k++)
                acc[i][j][k] = 0.f;

    fill(0);
    fill(1);

    #pragma unroll 1
    for (int kt = 0; kt < KITERS; kt++) {
        if (kt < KITERS - 1) cp_wait<1>(); else cp_wait<0>();
        __syncthreads();
        if (kt < KITERS - 2) fill(kt + 2);

        const uint32_t sbase = tileBase + (uint32_t)(kt % STAGES) * STAGE_BYTES;
        #pragma unroll
        for (int kk = 0; kk < 4; kk++) {
            uint32_t af[2][4], bf[8][2];
            const uint32_t cA = ((uint32_t)(kk * 2) + hbitA) ^ rsw;
            const uint32_t cB = ((uint32_t)(kk * 2) + hbitB) ^ rsw;
            ldmx4(af[0][0], af[0][1], af[0][2], af[0][3], sbase + aoff0 + (cA << 4));
            ldmx4(af[1][0], af[1][1], af[1][2], af[1][3], sbase + aoff0 + 2048u + (cA << 4));
            #pragma unroll
            for (int q = 0; q < 4; q++)
                ldmx4(bf[2 * q][0], bf[2 * q][1], bf[2 * q + 1][0], bf[2 * q + 1][1],
                      sbase + boff0 + (uint32_t)(q * 2048) + (cB << 4));
            #pragma unroll
            for (int im = 0; im < 2; im++)
                #pragma unroll
                for (int in = 0; in < 8; in++)
                    mma_f16(acc[im][in],
                            af[im][0], af[im][1], af[im][2], af[im][3],
                            bf[in][0], bf[in][1]);
        }
    }

    // Epilogue
    #pragma unroll
    for (int im = 0; im < 2; im++) {
        #pragma unroll
        for (int in = 0; in < 8; in++) {
            const int col = bn0 + wn * 64 + in * 8 + 2 * tg;
            const float b0 = __ldg(bias + col);
            const float b1 = __ldg(bias + col + 1);
            #pragma unroll
            for (int h = 0; h < 2; h++) {
                const long row = bm0 + wm * 32 + im * 16 + g + h * 8;
                float v0 = acc[im][in][2 * h + 0] + b0;
                float v1 = acc[im][in][2 * h + 1] + b1;
                if (epi == 3) {
                    const float2 st = __ldg(args.stats + row);
                    v0 = st.x * acc[im][in][2 * h + 0] - st.y * __ldg(args.gWo + col) + b0
                         + args.resid[row * N_DIM + col];
                    v1 = st.x * acc[im][in][2 * h + 1] - st.y * __ldg(args.gWo + col + 1) + b1
                         + args.resid[row * N_DIM + col + 1];
                    *(float2*)((float*)C + row * N_DIM + col) = make_float2(v0, v1);
                } else if (epi == 1) {
                    float p0 = tanhf(v0) * __ldg(args.ps + col);
                    float p1 = tanhf(v1) * __ldg(args.ps + col + 1);
                    float s0, c0, s1, c1;
                    __sincosf(p0, &s0, &c0);
                    __sincosf(p1, &s1, &c1);
                    __half2 h0 = __floats2half2_rn(c0, s0);
                    __half2 h1 = __floats2half2_rn(c1, s1);
                    uint2 pk = make_uint2(*(uint32_t*)&h0, *(uint32_t*)&h1);
                    *(uint2*)((uint32_t*)C + row * N_DIM + col) = pk;
                } else {
                    if (oh) {
                        *(__half2*)((__half*)C + row * N_DIM + col) = __floats2half2_rn(v0, v1);
                    } else {
                        *(float2*)((float*)C + row * N_DIM + col) = make_float2(v0, v1);
                    }
                }
            }
        }
    }
}

// ---------------- prep kernels ----------------
struct W4 { const float* w[4]; };

__global__ void __launch_bounds__(256)
wtrans_all_k(const W4 ws, __half* __restrict__ WT)
{
    __shared__ float t[32][33];
    static const int slot[4] = {0, 1, 2, 5};
    const float* W = ws.w[blockIdx.z];
    __half* D = WT + (long)slot[blockIdx.z] * 1048576;
    int bx = blockIdx.x * 32, by = blockIdx.y * 32;
    #pragma unroll
    for (int i = threadIdx.y; i < 32; i += 8)
        t[i][threadIdx.x] = W[(by + i) * 1024 + bx + threadIdx.x];
    __syncthreads();
    #pragma unroll
    for (int i = threadIdx.y; i < 32; i += 8)
        D[(bx + i) * 1024 + by + threadIdx.x] = __float2half_rn(t[threadIdx.x][i]);
}

__global__ void __launch_bounds__(256)
cvt2_h_k(const float* __restrict__ s0, __half* __restrict__ d0,
         const float* __restrict__ s1, __half* __restrict__ d1)
{
    const float* s = blockIdx.y ? s1 : s0;
    __half* d = blockIdx.y ? d1 : d0;
    long i = ((long)blockIdx.x * 256 + threadIdx.x) * 8;
    float4 v0 = *(const float4*)(s + i);
    float4 v1 = *(const float4*)(s + i + 4);
    __half2 h[4];
    h[0] = __floats2half2_rn(v0.x, v0.y);
    h[1] = __floats2half2_rn(v0.z, v0.w);
    h[2] = __floats2half2_rn(v1.x, v1.y);
    h[3] = __floats2half2_rn(v1.z, v1.w);
    *(uint4*)(d + i) = *(uint4*)h;
}

__global__ void __launch_bounds__(256)
cvt_h_k(const float* __restrict__ s, __half* __restrict__ d)
{
    long i = ((long)blockIdx.x * 256 + threadIdx.x) * 8;
    float4 v0 = *(const float4*)(s + i);
    float4 v1 = *(const float4*)(s + i + 4);
    __half2 h[4];
    h[0] = __floats2half2_rn(v0.x, v0.y);
    h[1] = __floats2half2_rn(v0.z, v0.w);
    h[2] = __floats2half2_rn(v1.x, v1.y);
    h[3] = __floats2half2_rn(v1.z, v1.w);
    *(uint4*)(d + i) = *(uint4*)h;
}

// GEMVs from fp16 transposed weights: one warp per column, half2 loads.
__global__ void __launch_bounds__(128)
gemv_prep_k(const __half* __restrict__ WoT, const __half* __restrict__ WkpT,
            const __half* __restrict__ WqpT,
            const float* __restrict__ g, const float* __restrict__ b,
            const float* __restrict__ bo,
            const float* __restrict__ bk, const float* __restrict__ bkp,
            const float* __restrict__ bq, const float* __restrict__ bqp,
            float* __restrict__ gWo, float* __restrict__ bWoBo,
            float* __restrict__ bck, float* __restrict__ bcq)
{
    const int lane = threadIdx.x & 31;
    const int col  = blockIdx.x * 4 + (threadIdx.x >> 5);
    const __half* wo  = WoT  + (long)col * 1024;
    const __half* wkp = WkpT + (long)col * 1024;
    const __half* wqp = WqpT + (long)col * 1024;
    float a1 = 0.f, a2 = 0.f, a3 = 0.f, a4 = 0.f;
    #pragma unroll 8
    for (int d = lane * 2; d < 1024; d += 64) {
        float2 w  = __half22float2(*(const __half2*)(wo + d));
        float2 wk = __half22float2(*(const __half2*)(wkp + d));
        float2 wq = __half22float2(*(const __half2*)(wqp + d));
        float2 gg = *(const float2*)(g + d);
        float2 bb = *(const float2*)(b + d);
        float2 kk = *(const float2*)(bk + d);
        float2 qq = *(const float2*)(bq + d);
        a1 = fmaf(gg.x, w.x, fmaf(gg.y, w.y, a1));
        a2 = fmaf(bb.x, w.x, fmaf(bb.y, w.y, a2));
        a3 = fmaf(kk.x, wk.x, fmaf(kk.y, wk.y, a3));
        a4 = fmaf(qq.x, wq.x, fmaf(qq.y, wq.y, a4));
    }
    #pragma unroll
    for (int o = 16; o; o >>= 1) {
        a1 += __shfl_xor_sync(0xffffffffu, a1, o);
        a2 += __shfl_xor_sync(0xffffffffu, a2, o);
        a3 += __shfl_xor_sync(0xffffffffu, a3, o);
        a4 += __shfl_xor_sync(0xffffffffu, a4, o);
    }
    if (lane == 0) {
        gWo[col]   = a1;
        bWoBo[col] = a2 + bo[col];
        bck[col]   = a3 + bkp[col];
        bcq[col]   = a4 + bqp[col];
    }
}

// ---------------- bind + chunk scan (pure FMA; cos/sin precomputed fp16x2) ----------------
__global__ void __launch_bounds__(256)
bind_scan_k(const __half* __restrict__ V, const uint32_t* __restrict__ KS,
            const uint32_t* __restrict__ QS, const float* __restrict__ lng,
            __half* __restrict__ R, float2* __restrict__ stats)
{
    __shared__ float2 part[64][8];
    const float inv = 0.03125f;  // 1/sqrt(1024)
    const int tid = threadIdx.x;
    const int lane = tid & 31, w = tid >> 5;
    long idx = (long)blockIdx.x * 64 * 1024 + tid * 4;
    float4 mr = make_float4(0.f, 0.f, 0.f, 0.f);
    float4 mi = make_float4(0.f, 0.f, 0.f, 0.f);
    const float4 gv = *(const float4*)(lng + tid * 4);

    #pragma unroll 4
    for (int s = 0; s < 64; s++, idx += 1024) {
        uint2 vpk = *(const uint2*)(V + idx);
        uint4 ks  = *(const uint4*)(KS + idx);
        uint4 qs  = *(const uint4*)(QS + idx);
        float2 va = __half22float2(*(__half2*)&vpk.x);
        float2 vb = __half22float2(*(__half2*)&vpk.y);
        float2 k0 = __half22float2(*(__half2*)&ks.x);
        float2 k1 = __half22float2(*(__half2*)&ks.y);
        float2 k2 = __half22float2(*(__half2*)&ks.z);
        float2 k3 = __half22float2(*(__half2*)&ks.w);
        float2 q0 = __half22float2(*(__half2*)&qs.x);
        float2 q1 = __half22float2(*(__half2*)&qs.y);
        float2 q2 = __half22float2(*(__half2*)&qs.z);
        float2 q3 = __half22float2(*(__half2*)&qs.w);
        float4 out;

        mr.x = fmaf(va.x, k0.x, mr.x); mi.x = fmaf(va.x, k0.y, mi.x);
        out.x = (mr.x * q0.x + mi.x * q0.y) * inv;
        mr.y = fmaf(va.y, k1.x, mr.y); mi.y = fmaf(va.y, k1.y, mi.y);
        out.y = (mr.y * q1.x + mi.y * q1.y) * inv;
        mr.z = fmaf(vb.x, k2.x, mr.z); mi.z = fmaf(vb.x, k2.y, mi.z);
        out.z = (mr.z * q2.x + mi.z * q2.y) * inv;
        mr.w = fmaf(vb.y, k3.x, mr.w); mi.w = fmaf(vb.y, k3.y, mi.w);
        out.w = (mr.w * q3.x + mi.w * q3.y) * inv;

        float rs = out.x + out.y + out.z + out.w;
        float rq = out.x * out.x + out.y * out.y + out.z * out.z + out.w * out.w;
        #pragma unroll
        for (int o = 16; o; o >>= 1) {
            rs += __shfl_xor_sync(0xffffffffu, rs, o);
            rq += __shfl_xor_sync(0xffffffffu, rq, o);
        }
        if (lane == 0) part[s][w] = make_float2(rs, rq);

        __half2 h0 = __floats2half2_rn(out.x * gv.x, out.y * gv.y);
        __half2 h1 = __floats2half2_rn(out.z * gv.z, out.w * gv.w);
        uint2 pk = make_uint2(*(uint32_t*)&h0, *(uint32_t*)&h1);
        *(uint2*)(R + idx) = pk;
    }
    __syncthreads();
    if (tid < 64) {
        float S = 0.f, Q = 0.f;
        #pragma unroll
        for (int i = 0; i < 8; i++) { S += part[tid][i].x; Q += part[tid][i].y; }
        float mu = S * (1.f / 1024.f);
        float var = Q * (1.f / 1024.f) - mu * mu;
        float rstd = rsqrtf(var + 1e-5f);
        stats[blockIdx.x * 64 + tid] = make_float2(rstd, mu * rstd);
    }
}

extern "C" void kernel_launch(void* const* d_in, const int* in_sizes, int n_in,
                              void* d_out, int out_size)
{
    const float* x   = (const float*)d_in[0];
    const float* Wk  = (const float*)d_in[1];
    const float* bk  = (const float*)d_in[2];
    const float* Wv  = (const float*)d_in[3];
    const float* bv  = (const float*)d_in[4];
    const float* Wq  = (const float*)d_in[5];
    const float* bq  = (const float*)d_in[6];
    const float* Wkp = (const float*)d_in[7];
    const float* bkp = (const float*)d_in[8];
    const float* Wqp = (const float*)d_in[9];
    const float* bqp = (const float*)d_in[10];
    const float* ps  = (const float*)d_in[11];
    const float* lng = (const float*)d_in[12];
    const float* lnb = (const float*)d_in[13];
    const float* Wo  = (const float*)d_in[14];
    const float* bo  = (const float*)d_in[15];
    float* out = (float*)d_out;

    const int M = in_sizes[0] / 1024;  // 32768
    const int MH = M / 2;              // 16384
    const long HOFF = (long)MH * 1024; // element offset for half 2

    uint32_t *pKS, *pQS;
    __half *pVh, *pR, *pX, *pWT, *pWkR, *pWqR;
    float *pgWo, *pbWoBo, *pbck, *pbcq, *pzero;
    float2* pStats;
    cudaGetSymbolAddress((void**)&pVh,  g_Vh);
    cudaGetSymbolAddress((void**)&pKS,  g_KS);
    cudaGetSymbolAddress((void**)&pQS,  g_QS);
    cudaGetSymbolAddress((void**)&pR,   g_R);
    cudaGetSymbolAddress((void**)&pX,   g_X);
    cudaGetSymbolAddress((void**)&pWT,  g_WT);
    cudaGetSymbolAddress((void**)&pWkR, g_WkR);
    cudaGetSymbolAddress((void**)&pWqR, g_WqR);
    cudaGetSymbolAddress((void**)&pStats, g_stats);
    cudaGetSymbolAddress((void**)&pgWo, g_gWo);
    cudaGetSymbolAddress((void**)&pbWoBo, g_bWoBo);
    cudaGetSymbolAddress((void**)&pbck, g_bck);
    cudaGetSymbolAddress((void**)&pbcq, g_bcq);
    cudaGetSymbolAddress((void**)&pzero, g_zero);

    cudaFuncSetAttribute(gemm_rt, cudaFuncAttributeMaxDynamicSharedMemorySize, SMEM_TOTAL);

    // ---- single extra stream (R12 footprint); s2 doubles as prep branch and
    //      half-1 scan/final pipeline stage ----
    cudaStream_t s2;
    cudaStreamCreateWithFlags(&s2, cudaStreamNonBlocking);
    cudaEvent_t ev0, evW, evG, evM1, evJ;
    cudaEventCreateWithFlags(&ev0, cudaEventDisableTiming);
    cudaEventCreateWithFlags(&evW, cudaEventDisableTiming);
    cudaEventCreateWithFlags(&evG, cudaEventDisableTiming);
    cudaEventCreateWithFlags(&evM1, cudaEventDisableTiming);
    cudaEventCreateWithFlags(&evJ, cudaEventDisableTiming);

    cudaEventRecord(ev0, 0);
    cudaStreamWaitEvent(s2, ev0, 0);

    cvt_h_k<<<NELEM / 2048, 256, 0, s2>>>(x, pX);

    W4 ws;
    ws.w[0] = Wv; ws.w[1] = Wkp; ws.w[2] = Wqp; ws.w[3] = Wo;
    cvt2_h_k<<<dim3(512, 2), 256>>>(Wk, pWkR, Wq, pWqR);
    wtrans_all_k<<<dim3(32, 32, 4), dim3(32, 8)>>>(ws, pWT);
    cudaEventRecord(evW, 0);
    cudaStreamWaitEvent(s2, evW, 0);

    gemv_prep_k<<<256, 128, 0, s2>>>(pWT + 5 * 1048576, pWT + 1 * 1048576, pWT + 2 * 1048576,
                                     lng, lnb, bo, bk, bkp, bq, bqp,
                                     pgWo, pbWoBo, pbck, pbcq);
    cudaEventRecord(evG, s2);

    GArgs a{};
    a.ps = ps; a.gWo = pgWo;

    // Weight composition (default stream)
    a.A[0] = pWT + 1 * 1048576; a.A[1] = pWT + 2 * 1048576; a.A[2] = a.A[1];
    a.W[0] = pWkR;              a.W[1] = pWqR;              a.W[2] = a.W[1];
    a.b[0] = pzero; a.b[1] = pzero; a.b[2] = pzero;
    a.C[0] = pWT + 3 * 1048576; a.C[1] = pWT + 4 * 1048576; a.C[2] = a.C[1];
    a.epi[0] = 0; a.epi[1] = 0; a.epi[2] = 0;
    a.oh[0] = 1; a.oh[1] = 1; a.oh[2] = 1;
    gemm_rt<<<dim3(8, 8, 2), 256, SMEM_TOTAL>>>(a);

    cudaStreamWaitEvent(0, evG, 0);

    // ---- split-M pipeline (s2 is idle after gemv) ----
    GArgs b1{};
    b1.ps = ps; b1.gWo = pgWo;
    b1.A[0] = pX; b1.A[1] = pX; b1.A[2] = pX;
    b1.W[0] = pWT + 0 * 1048576; b1.W[1] = pWT + 3 * 1048576; b1.W[2] = pWT + 4 * 1048576;
    b1.b[0] = bv; b1.b[1] = pbck; b1.b[2] = pbcq;
    b1.C[0] = pVh; b1.C[1] = pKS; b1.C[2] = pQS;
    b1.epi[0] = 0; b1.epi[1] = 1; b1.epi[2] = 1;
    b1.oh[0] = 1; b1.oh[1] = 0; b1.oh[2] = 0;
    gemm_rt<<<dim3(N_DIM / NT, MH / MT, 3), 256, SMEM_TOTAL>>>(b1);
    cudaEventRecord(evM1, 0);

    // Big batch half 2 (default stream; overlaps s2's scan/final of half 1)
    GArgs b2 = b1;
    b2.A[0] = pX + HOFF; b2.A[1] = b2.A[0]; b2.A[2] = b2.A[0];
    b2.C[0] = pVh + HOFF; b2.C[1] = pKS + HOFF; b2.C[2] = pQS + HOFF;
    gemm_rt<<<dim3(N_DIM / NT, MH / MT, 3), 256, SMEM_TOTAL>>>(b2);

    // s2: scan + final for half 1
    cudaStreamWaitEvent(s2, evM1, 0);
    bind_scan_k<<<MH / 64, 256, 0, s2>>>(pVh, pKS, pQS, lng, pR, pStats);

    GArgs f1{};
    f1.ps = ps; f1.gWo = pgWo;
    f1.A[0] = pR; f1.A[1] = pR; f1.A[2] = pR;
    f1.W[0] = pWT + 5 * 1048576; f1.W[1] = f1.W[0]; f1.W[2] = f1.W[0];
    f1.b[0] = pbWoBo; f1.b[1] = pbWoBo; f1.b[2] = pbWoBo;
    f1.C[0] = out; f1.C[1] = out; f1.C[2] = out;
    f1.epi[0] = 3; f1.epi[1] = 3; f1.epi[2] = 3;
    f1.oh[0] = 0; f1.oh[1] = 0; f1.oh[2] = 0;
    f1.resid = x; f1.stats = pStats;
    gemm_rt<<<dim3(N_DIM / NT, MH / MT, 1), 256, SMEM_TOTAL, s2>>>(f1);
    cudaEventRecord(evJ, s2);

    // default stream: scan + final for half 2
    bind_scan_k<<<MH / 64, 256>>>(pVh + HOFF, pKS + HOFF, pQS + HOFF, lng,
                                  pR + HOFF, pStats + MH);

    GArgs f2 = f1;
    f2.A[0] = pR + HOFF; f2.A[1] = f2.A[0]; f2.A[2] = f2.A[0];
    f2.C[0] = out + HOFF; f2.C[1] = f2.C[0]; f2.C[2] = f2.C[0];
    f2.resid = x + HOFF; f2.stats = pStats + MH;
    gemm_rt<<<dim3(N_DIM / NT, MH / MT, 1), 256, SMEM_TOTAL>>>(f2);

    // join s2 back into origin stream
    cudaStreamWaitEvent(0, evJ, 0);
}